// round 2
// baseline (speedup 1.0000x reference)
#include <cuda_runtime.h>
#include <cstdint>
#include <math.h>

#define TT 256
#define BB 64
#define XX 512
#define HH 2048
#define G4 8192   // 4*HH

// ---------------- device scratch (static; no allocations allowed) ----------
__device__ float g_xproj[(size_t)TT * BB * G4];  // 512 MB: x@W_ih^T + b_ih + b_hh
__device__ float g_h[2][BB * HH];                // ping-pong hidden state
__device__ float g_c[BB * HH];                   // cell state (in-place per block)

// ---------------- small PTX helpers ----------------------------------------
__device__ __forceinline__ uint32_t f2tf(float x) {
    uint32_t u;
    asm("cvt.rna.tf32.f32 %0, %1;" : "=r"(u) : "f"(x));
    return u;
}

__device__ __forceinline__ void mma8(float* d, const uint32_t* a, const uint32_t* b) {
    asm volatile(
        "mma.sync.aligned.m16n8k8.row.col.f32.tf32.tf32.f32 "
        "{%0,%1,%2,%3},{%4,%5,%6,%7},{%8,%9},{%0,%1,%2,%3};"
        : "+f"(d[0]), "+f"(d[1]), "+f"(d[2]), "+f"(d[3])
        : "r"(a[0]), "r"(a[1]), "r"(a[2]), "r"(a[3]), "r"(b[0]), "r"(b[1]));
}

__device__ __forceinline__ void cpa16(uint32_t smem_addr, const void* gptr) {
    asm volatile("cp.async.ca.shared.global [%0], [%1], 16;"
                 :: "r"(smem_addr), "l"(gptr));
}
__device__ __forceinline__ void cp_commit() { asm volatile("cp.async.commit_group;"); }
template <int N>
__device__ __forceinline__ void cp_wait() { asm volatile("cp.async.wait_group %0;" :: "n"(N)); }

// ===========================================================================
// Kernel 1: x_proj[t*B+b, :] = input[t,b,:] @ w_ih^T + b_ih + b_hh
// M = T*B = 16384, N = 4H = 8192, K = X = 512.  Block tile 64x64, KC=32.
// ===========================================================================
__global__ void __launch_bounds__(256) xproj_kernel(
    const float* __restrict__ A,    // [16384, 512]
    const float* __restrict__ W,    // [8192, 512]
    const float* __restrict__ bih,
    const float* __restrict__ bhh)
{
    __shared__ float As[2][64][36];
    __shared__ float Bs[2][64][36];

    const int tid = threadIdx.x;
    const int m0 = blockIdx.y * 64;
    const int n0 = blockIdx.x * 64;
    const int warp = tid >> 5, lane = tid & 31;
    const int wm = warp & 3, wn = warp >> 2;        // 4 x 2 warp grid
    const int g = lane >> 2, tg = lane & 3;
    const int m_base = wm * 16, n_base = wn * 32;

    float acc[4][4];
    #pragma unroll
    for (int i = 0; i < 4; ++i)
        #pragma unroll
        for (int j = 0; j < 4; ++j) acc[i][j] = 0.f;

    const int NCH = XX / 32;  // 16 chunks

    // prologue: chunk 0
    {
        const int k0 = 0;
        #pragma unroll
        for (int rep = 0; rep < 2; ++rep) {
            int q = tid + rep * 256;
            int r = q >> 3, kq = q & 7;
            cpa16((uint32_t)__cvta_generic_to_shared(&As[0][r][kq * 4]),
                  A + (size_t)(m0 + r) * XX + k0 + kq * 4);
            cpa16((uint32_t)__cvta_generic_to_shared(&Bs[0][r][kq * 4]),
                  W + (size_t)(n0 + r) * XX + k0 + kq * 4);
        }
        cp_commit();
    }

    for (int ch = 0; ch < NCH; ++ch) {
        if (ch + 1 < NCH) {
            const int k0 = (ch + 1) * 32;
            const int nb = (ch + 1) & 1;
            #pragma unroll
            for (int rep = 0; rep < 2; ++rep) {
                int q = tid + rep * 256;
                int r = q >> 3, kq = q & 7;
                cpa16((uint32_t)__cvta_generic_to_shared(&As[nb][r][kq * 4]),
                      A + (size_t)(m0 + r) * XX + k0 + kq * 4);
                cpa16((uint32_t)__cvta_generic_to_shared(&Bs[nb][r][kq * 4]),
                      W + (size_t)(n0 + r) * XX + k0 + kq * 4);
            }
            cp_commit();
            cp_wait<1>();
        } else {
            cp_wait<0>();
        }
        __syncthreads();

        const int cb = ch & 1;
        #pragma unroll
        for (int kk = 0; kk < 32; kk += 8) {
            uint32_t af[4];
            af[0] = f2tf(As[cb][m_base + g][kk + tg]);
            af[1] = f2tf(As[cb][m_base + g + 8][kk + tg]);
            af[2] = f2tf(As[cb][m_base + g][kk + tg + 4]);
            af[3] = f2tf(As[cb][m_base + g + 8][kk + tg + 4]);
            #pragma unroll
            for (int nt = 0; nt < 4; ++nt) {
                uint32_t bf[2];
                const int n = n_base + nt * 8 + g;
                bf[0] = f2tf(Bs[cb][n][kk + tg]);
                bf[1] = f2tf(Bs[cb][n][kk + tg + 4]);
                mma8(acc[nt], af, bf);
            }
        }
        __syncthreads();
    }

    // epilogue: += bias, write to g_xproj
    #pragma unroll
    for (int nt = 0; nt < 4; ++nt) {
        const int col = n0 + n_base + nt * 8 + tg * 2;
        const float b0 = bih[col] + bhh[col];
        const float b1 = bih[col + 1] + bhh[col + 1];
        const int row = m0 + m_base + g;
        g_xproj[(size_t)row * G4 + col]           = acc[nt][0] + b0;
        g_xproj[(size_t)row * G4 + col + 1]       = acc[nt][1] + b1;
        g_xproj[(size_t)(row + 8) * G4 + col]     = acc[nt][2] + b0;
        g_xproj[(size_t)(row + 8) * G4 + col + 1] = acc[nt][3] + b1;
    }
}

// ===========================================================================
// Kernel 2: one LSTM step. 128 blocks; block owns 16 hidden units x 4 gates
// (64 gate-columns), all 64 batches. gates = h_prev @ W_hh^T (+x_proj), then
// fused elementwise c/h update. Raw h_t written to ys (softmax later).
// ===========================================================================
__global__ void __launch_bounds__(256) step_kernel(
    const float* __restrict__ h0,    // initial hidden (used when t==0)
    const float* __restrict__ Whh,   // [8192, 2048]
    int t,
    float* __restrict__ out)         // d_out base
{
    __shared__ float As[2][64][36];  // h tile  [batch][k]
    __shared__ float Bs[2][64][36];  // W tile  [col][k]

    const int tid = threadIdx.x;
    const int j0 = blockIdx.x * 16;
    const int warp = tid >> 5, lane = tid & 31;
    const int wm = warp & 3, wn = warp >> 2;
    const int g = lane >> 2, tg = lane & 3;
    const int m_base = wm * 16, n_base = wn * 32;

    const float* __restrict__ h_in = (t == 0) ? h0 : g_h[(t + 1) & 1];
    float* __restrict__ h_out = g_h[t & 1];
    float* __restrict__ ys = out + (size_t)t * BB * HH;

    float acc[4][4];
    #pragma unroll
    for (int i = 0; i < 4; ++i)
        #pragma unroll
        for (int j = 0; j < 4; ++j) acc[i][j] = 0.f;

    const int NCH = HH / 32;  // 64 chunks

    // prologue
    {
        #pragma unroll
        for (int rep = 0; rep < 2; ++rep) {
            int q = tid + rep * 256;
            int r = q >> 3, kq = q & 7;
            cpa16((uint32_t)__cvta_generic_to_shared(&As[0][r][kq * 4]),
                  h_in + (size_t)r * HH + kq * 4);
            const int rw = (r >> 4) * HH + j0 + (r & 15);  // gate-interleaved row
            cpa16((uint32_t)__cvta_generic_to_shared(&Bs[0][r][kq * 4]),
                  Whh + (size_t)rw * HH + kq * 4);
        }
        cp_commit();
    }

    for (int ch = 0; ch < NCH; ++ch) {
        if (ch + 1 < NCH) {
            const int k0 = (ch + 1) * 32;
            const int nb = (ch + 1) & 1;
            #pragma unroll
            for (int rep = 0; rep < 2; ++rep) {
                int q = tid + rep * 256;
                int r = q >> 3, kq = q & 7;
                cpa16((uint32_t)__cvta_generic_to_shared(&As[nb][r][kq * 4]),
                      h_in + (size_t)r * HH + k0 + kq * 4);
                const int rw = (r >> 4) * HH + j0 + (r & 15);
                cpa16((uint32_t)__cvta_generic_to_shared(&Bs[nb][r][kq * 4]),
                      Whh + (size_t)rw * HH + k0 + kq * 4);
            }
            cp_commit();
            cp_wait<1>();
        } else {
            cp_wait<0>();
        }
        __syncthreads();

        const int cb = ch & 1;
        #pragma unroll
        for (int kk = 0; kk < 32; kk += 8) {
            uint32_t af[4];
            af[0] = f2tf(As[cb][m_base + g][kk + tg]);
            af[1] = f2tf(As[cb][m_base + g + 8][kk + tg]);
            af[2] = f2tf(As[cb][m_base + g][kk + tg + 4]);
            af[3] = f2tf(As[cb][m_base + g + 8][kk + tg + 4]);
            #pragma unroll
            for (int nt = 0; nt < 4; ++nt) {
                uint32_t bf[2];
                const int n = n_base + nt * 8 + g;
                bf[0] = f2tf(Bs[cb][n][kk + tg]);
                bf[1] = f2tf(Bs[cb][n][kk + tg + 4]);
                mma8(acc[nt], af, bf);
            }
        }
        __syncthreads();
    }

    // stage raw gates into smem (reuse As region: 4096 floats <= 4608)
    float* gs = &As[0][0][0];
    #pragma unroll
    for (int nt = 0; nt < 4; ++nt) {
        const int col = n_base + nt * 8 + tg * 2;
        const int row = m_base + g;
        gs[row * 64 + col]           = acc[nt][0];
        gs[row * 64 + col + 1]       = acc[nt][1];
        gs[(row + 8) * 64 + col]     = acc[nt][2];
        gs[(row + 8) * 64 + col + 1] = acc[nt][3];
    }
    __syncthreads();

    // fused elementwise LSTM update: 64 batches x 16 hidden = 1024 items
    const float* __restrict__ xp = g_xproj + (size_t)t * BB * G4;
    #pragma unroll
    for (int it = 0; it < 4; ++it) {
        const int idx = tid + it * 256;
        const int b = idx >> 4, jl = idx & 15;
        const int j = j0 + jl;
        const size_t xb = (size_t)b * G4 + j;
        const float iv = gs[b * 64 + jl]      + xp[xb];
        const float fv = gs[b * 64 + 16 + jl] + xp[xb + HH];
        const float gv = gs[b * 64 + 32 + jl] + xp[xb + 2 * HH];
        const float ov = gs[b * 64 + 48 + jl] + xp[xb + 3 * HH];

        const float si = 1.f / (1.f + expf(-iv));
        const float sf = 1.f / (1.f + expf(-fv));
        const float tgh = tanhf(gv);
        const float so = 1.f / (1.f + expf(-ov));

        const float cprev = g_c[b * HH + j];
        const float cn = sf * cprev + si * tgh;
        const float hn = so * tanhf(cn);

        g_c[b * HH + j] = cn;
        h_out[b * HH + j] = hn;
        ys[(size_t)b * HH + j] = hn;  // raw h; softmax pass normalizes later
    }
}

// ===========================================================================
// Kernel 3: in-place row softmax over ys: 16384 rows x 2048
// ===========================================================================
__global__ void __launch_bounds__(256) softmax_kernel(float* __restrict__ out)
{
    const size_t base = (size_t)blockIdx.x * HH;
    const int tid = threadIdx.x;
    const int warp = tid >> 5, lane = tid & 31;
    __shared__ float red[8];

    float v[8];
    #pragma unroll
    for (int i = 0; i < 8; ++i) v[i] = out[base + tid + i * 256];

    float m = v[0];
    #pragma unroll
    for (int i = 1; i < 8; ++i) m = fmaxf(m, v[i]);
    #pragma unroll
    for (int off = 16; off > 0; off >>= 1)
        m = fmaxf(m, __shfl_xor_sync(0xFFFFFFFFu, m, off));
    if (lane == 0) red[warp] = m;
    __syncthreads();
    float bm = red[0];
    #pragma unroll
    for (int i = 1; i < 8; ++i) bm = fmaxf(bm, red[i]);
    __syncthreads();

    float e[8];
    float s = 0.f;
    #pragma unroll
    for (int i = 0; i < 8; ++i) { e[i] = expf(v[i] - bm); s += e[i]; }
    #pragma unroll
    for (int off = 16; off > 0; off >>= 1)
        s += __shfl_xor_sync(0xFFFFFFFFu, s, off);
    if (lane == 0) red[warp] = s;
    __syncthreads();
    float bs = 0.f;
    #pragma unroll
    for (int i = 0; i < 8; ++i) bs += red[i];
    const float inv = 1.f / bs;

    #pragma unroll
    for (int i = 0; i < 8; ++i) out[base + tid + i * 256] = e[i] * inv;
}

// ===========================================================================
// Kernel 4: init c buffer; Kernel 5: write h_T, c_T tail
// ===========================================================================
__global__ void init_c_kernel(const float* __restrict__ c0)
{
    const int i = blockIdx.x * blockDim.x + threadIdx.x;
    if (i < BB * HH) g_c[i] = c0[i];
}

__global__ void tail_kernel(float* __restrict__ out)
{
    const int i = blockIdx.x * blockDim.x + threadIdx.x;
    if (i < BB * HH) {
        out[(size_t)TT * BB * HH + i] = g_h[(TT - 1) & 1][i];
        out[(size_t)TT * BB * HH + BB * HH + i] = g_c[i];
    }
}

// ===========================================================================
extern "C" void kernel_launch(void* const* d_in, const int* in_sizes, int n_in,
                              void* d_out, int out_size)
{
    (void)in_sizes; (void)n_in; (void)out_size;
    const float* input = (const float*)d_in[0];  // [T,B,X]
    const float* h0    = (const float*)d_in[1];  // [B,H]
    const float* c0    = (const float*)d_in[2];  // [B,H]
    const float* wih   = (const float*)d_in[3];  // [4H,X]
    const float* whh   = (const float*)d_in[4];  // [4H,H]
    const float* bih   = (const float*)d_in[5];  // [4H]
    const float* bhh   = (const float*)d_in[6];  // [4H]
    float* out = (float*)d_out;

    init_c_kernel<<<(BB * HH + 255) / 256, 256>>>(c0);

    xproj_kernel<<<dim3(G4 / 64, (TT * BB) / 64), 256>>>(input, wih, bih, bhh);

    for (int t = 0; t < TT; ++t)
        step_kernel<<<HH / 16, 256>>>(h0, whh, t, out);

    softmax_kernel<<<TT * BB, 256>>>(out);

    tail_kernel<<<(BB * HH + 255) / 256, 256>>>(out);
}

// round 3
// speedup vs baseline: 2.0826x; 2.0826x over previous
#include <cuda_runtime.h>
#include <cuda_fp16.h>
#include <cstdint>
#include <math.h>

#define TT 256
#define BB 64
#define XX 512
#define HH 2048
#define G4 8192   // 4*HH

// ---------------- device scratch (static; no allocations allowed) ----------
__device__ __align__(128) float  g_xproj[(size_t)TT * BB * G4]; // 512 MB
__device__ __align__(128) __half g_hh[2][BB * HH];              // fp16 hidden ping-pong
__device__ __align__(128) float  g_c[BB * HH];                  // cell state fp32
__device__ __align__(128) __half g_Wp[(size_t)G4 * HH];         // reordered fp16 W_hh (32 MB)
__device__ __align__(128) __half g_xin[(size_t)TT * BB * XX];   // fp16 input
__device__ __align__(128) __half g_wih[(size_t)G4 * XX];        // fp16 w_ih

// ---------------- PTX helpers ----------------------------------------------
__device__ __forceinline__ void mma16(float* d, const uint32_t* a, const uint32_t* b) {
    asm volatile(
        "mma.sync.aligned.m16n8k16.row.col.f32.f16.f16.f32 "
        "{%0,%1,%2,%3},{%4,%5,%6,%7},{%8,%9},{%0,%1,%2,%3};"
        : "+f"(d[0]), "+f"(d[1]), "+f"(d[2]), "+f"(d[3])
        : "r"(a[0]), "r"(a[1]), "r"(a[2]), "r"(a[3]), "r"(b[0]), "r"(b[1]));
}

__device__ __forceinline__ void cpa16(uint32_t smem_addr, const void* gptr) {
    asm volatile("cp.async.ca.shared.global [%0], [%1], 16;"
                 :: "r"(smem_addr), "l"(gptr));
}
__device__ __forceinline__ void cp_commit() { asm volatile("cp.async.commit_group;"); }
template <int N>
__device__ __forceinline__ void cp_wait() { asm volatile("cp.async.wait_group %0;" :: "n"(N)); }

// ===========================================================================
// Prep kernels (run once per launch; cheap)
// ===========================================================================
__global__ void init_state_kernel(const float* __restrict__ h0,
                                  const float* __restrict__ c0)
{
    const int i = blockIdx.x * blockDim.x + threadIdx.x;
    if (i < BB * HH) {
        g_c[i] = c0[i];
        g_hh[1][i] = __float2half_rn(h0[i]);   // step t=0 reads g_hh[1]
    }
}

__global__ void conv_f2h_kernel(__half* __restrict__ dst,
                                const float* __restrict__ src, int n2)
{
    const int i = blockIdx.x * blockDim.x + threadIdx.x;
    if (i < n2) {
        float2 v = ((const float2*)src)[i];
        ((__half2*)dst)[i] = __float22half2_rn(v);
    }
}

// Reorder W_hh [8192,2048] fp32 -> g_Wp fp16, layout:
//   g_Wp[ ((jb*64 + chunk)*64 + r)*32 + kin ]
// where block jb owns hidden units [jb*16, jb*16+16), local row r -> global
// row (r>>4)*2048 + jb*16 + (r&15); chunk = k0/32.
__global__ void __launch_bounds__(256) reorder_whh_kernel(const float* __restrict__ W)
{
    const int bx = blockIdx.x;           // jb*64 + chunk
    const int jb = bx >> 6, chunk = bx & 63;
    const int tid = threadIdx.x;
    const int r = tid >> 2, kq = tid & 3;
    const int kin = kq * 8;
    const int grow = (r >> 4) * HH + jb * 16 + (r & 15);
    const float* s = W + (size_t)grow * HH + chunk * 32 + kin;
    float4 v0 = *(const float4*)s;
    float4 v1 = *(const float4*)(s + 4);
    __half2 h[4];
    h[0] = __float22half2_rn(make_float2(v0.x, v0.y));
    h[1] = __float22half2_rn(make_float2(v0.z, v0.w));
    h[2] = __float22half2_rn(make_float2(v1.x, v1.y));
    h[3] = __float22half2_rn(make_float2(v1.z, v1.w));
    *(uint4*)(g_Wp + ((size_t)bx * 64 + r) * 32 + kin) = *(uint4*)h;
}

// ===========================================================================
// Kernel 1: x_proj = input @ w_ih^T + b_ih + b_hh   (fp16 MMA, 128x128 tiles)
// M=16384, N=8192, K=512, KC=32, 2 stages.
// ===========================================================================
__global__ void __launch_bounds__(256) xproj_kernel(
    const float* __restrict__ bih, const float* __restrict__ bhh)
{
    __shared__ __align__(16) __half sm[2][2][128 * 40];   // [stage][A/B][tile]

    const int tid = threadIdx.x;
    const int m0 = blockIdx.y * 128;
    const int n0 = blockIdx.x * 128;
    const int warp = tid >> 5, lane = tid & 31;
    const int wm = warp & 3, wn = warp >> 2;         // 4m x 2n warps
    const int g = lane >> 2, tg = lane & 3;

    float acc[2][8][4];
    #pragma unroll
    for (int a = 0; a < 2; ++a)
        #pragma unroll
        for (int b = 0; b < 8; ++b)
            #pragma unroll
            for (int c = 0; c < 4; ++c) acc[a][b][c] = 0.f;

    const __half* A = g_xin;    // [16384,512]
    const __half* B = g_wih;    // [8192,512]
    const int NCH = XX / 32;    // 16

    auto issue = [&](int ch) {
        const int st = ch & 1;
        const int k0 = ch * 32;
        #pragma unroll
        for (int rep = 0; rep < 2; ++rep) {
            const int q = tid + rep * 256;
            const int r = q >> 2, kq = q & 3;
            cpa16((uint32_t)__cvta_generic_to_shared(&sm[st][0][r * 40 + kq * 8]),
                  A + (size_t)(m0 + r) * XX + k0 + kq * 8);
            cpa16((uint32_t)__cvta_generic_to_shared(&sm[st][1][r * 40 + kq * 8]),
                  B + (size_t)(n0 + r) * XX + k0 + kq * 8);
        }
    };

    issue(0); cp_commit();

    for (int ch = 0; ch < NCH; ++ch) {
        if (ch + 1 < NCH) issue(ch + 1);
        cp_commit();
        cp_wait<1>();
        __syncthreads();

        const __half* As = sm[ch & 1][0];
        const __half* Bs = sm[ch & 1][1];
        #pragma unroll
        for (int kk = 0; kk < 32; kk += 16) {
            #pragma unroll
            for (int mt = 0; mt < 2; ++mt) {
                uint32_t af[4];
                const int mr = wm * 32 + mt * 16 + g;
                af[0] = *(const uint32_t*)&As[mr * 40 + kk + tg * 2];
                af[1] = *(const uint32_t*)&As[(mr + 8) * 40 + kk + tg * 2];
                af[2] = *(const uint32_t*)&As[mr * 40 + kk + tg * 2 + 8];
                af[3] = *(const uint32_t*)&As[(mr + 8) * 40 + kk + tg * 2 + 8];
                #pragma unroll
                for (int nt = 0; nt < 8; ++nt) {
                    uint32_t bf[2];
                    const int nr = wn * 64 + nt * 8 + g;
                    bf[0] = *(const uint32_t*)&Bs[nr * 40 + kk + tg * 2];
                    bf[1] = *(const uint32_t*)&Bs[nr * 40 + kk + tg * 2 + 8];
                    mma16(acc[mt][nt], af, bf);
                }
            }
        }
        __syncthreads();
    }

    #pragma unroll
    for (int mt = 0; mt < 2; ++mt) {
        #pragma unroll
        for (int nt = 0; nt < 8; ++nt) {
            const int col = n0 + wn * 64 + nt * 8 + tg * 2;
            const float b0 = bih[col] + bhh[col];
            const float b1 = bih[col + 1] + bhh[col + 1];
            const int row = m0 + wm * 32 + mt * 16 + g;
            g_xproj[(size_t)row * G4 + col]           = acc[mt][nt][0] + b0;
            g_xproj[(size_t)row * G4 + col + 1]       = acc[mt][nt][1] + b1;
            g_xproj[(size_t)(row + 8) * G4 + col]     = acc[mt][nt][2] + b0;
            g_xproj[(size_t)(row + 8) * G4 + col + 1] = acc[mt][nt][3] + b1;
        }
    }
}

// ===========================================================================
// Kernel 2: one LSTM step (fp16 MMA, 4-stage cp.async pipeline).
// 128 blocks; block jb owns 16 hidden units x 4 gates = 64 gate columns,
// all 64 batches. M=64, N=64, K=2048, KC=32.
// ===========================================================================
__global__ void __launch_bounds__(256) step_kernel(int t, float* __restrict__ out)
{
    __shared__ __align__(16) __half sm[4][2][64 * 40];   // 40,960 B

    const int tid = threadIdx.x;
    const int jb = blockIdx.x;
    const int j0 = jb * 16;
    const int warp = tid >> 5, lane = tid & 31;
    const int wm = warp & 3, wn = warp >> 2;             // 4m x 2n
    const int g = lane >> 2, tg = lane & 3;
    const int m_base = wm * 16, n_base = wn * 32;

    const __half* __restrict__ h_in = g_hh[(t + 1) & 1];
    __half* __restrict__ h_out = g_hh[t & 1];
    float* __restrict__ ys = out + (size_t)t * BB * HH;
    const __half* __restrict__ Wb = g_Wp + (size_t)jb * 64 * HH;  // per-block slab

    float acc[4][4];
    #pragma unroll
    for (int i = 0; i < 4; ++i)
        #pragma unroll
        for (int j = 0; j < 4; ++j) acc[i][j] = 0.f;

    const int NCH = HH / 32;   // 64 chunks
    const int r = tid >> 2, kq = tid & 3;

    auto issue = [&](int ch) {
        const int st = ch & 3;
        const int k0 = ch * 32;
        cpa16((uint32_t)__cvta_generic_to_shared(&sm[st][0][r * 40 + kq * 8]),
              h_in + (size_t)r * HH + k0 + kq * 8);
        cpa16((uint32_t)__cvta_generic_to_shared(&sm[st][1][r * 40 + kq * 8]),
              Wb + ((size_t)ch * 64 + r) * 32 + kq * 8);
    };

    issue(0); cp_commit();
    issue(1); cp_commit();
    issue(2); cp_commit();

    for (int ch = 0; ch < NCH; ++ch) {
        cp_wait<2>();
        __syncthreads();

        const __half* As = sm[ch & 3][0];
        const __half* Bs = sm[ch & 3][1];
        #pragma unroll
        for (int kk = 0; kk < 32; kk += 16) {
            uint32_t af[4];
            af[0] = *(const uint32_t*)&As[(m_base + g) * 40 + kk + tg * 2];
            af[1] = *(const uint32_t*)&As[(m_base + g + 8) * 40 + kk + tg * 2];
            af[2] = *(const uint32_t*)&As[(m_base + g) * 40 + kk + tg * 2 + 8];
            af[3] = *(const uint32_t*)&As[(m_base + g + 8) * 40 + kk + tg * 2 + 8];
            #pragma unroll
            for (int nt = 0; nt < 4; ++nt) {
                uint32_t bf[2];
                const int nr = n_base + nt * 8 + g;
                bf[0] = *(const uint32_t*)&Bs[nr * 40 + kk + tg * 2];
                bf[1] = *(const uint32_t*)&Bs[nr * 40 + kk + tg * 2 + 8];
                mma16(acc[nt], af, bf);
            }
        }

        if (ch + 3 < NCH) issue(ch + 3);
        cp_commit();   // always commit (possibly empty group) to keep wait<2> exact
    }

    cp_wait<0>();
    __syncthreads();

    // stage gates into smem (alias pipeline buffers: need 16 KB <= 40 KB)
    float* gs = (float*)&sm[0][0][0];
    #pragma unroll
    for (int nt = 0; nt < 4; ++nt) {
        const int col = n_base + nt * 8 + tg * 2;
        const int row = m_base + g;
        gs[row * 64 + col]           = acc[nt][0];
        gs[row * 64 + col + 1]       = acc[nt][1];
        gs[(row + 8) * 64 + col]     = acc[nt][2];
        gs[(row + 8) * 64 + col + 1] = acc[nt][3];
    }
    __syncthreads();

    // fused elementwise LSTM update: 64 batches x 16 hidden = 1024 items
    const float* __restrict__ xp = g_xproj + (size_t)t * BB * G4;
    #pragma unroll
    for (int it = 0; it < 4; ++it) {
        const int idx = tid + it * 256;
        const int b = idx >> 4, jl = idx & 15;
        const int j = j0 + jl;
        const size_t xb = (size_t)b * G4 + j;
        const float iv = gs[b * 64 + jl]      + xp[xb];
        const float fv = gs[b * 64 + 16 + jl] + xp[xb + HH];
        const float gv = gs[b * 64 + 32 + jl] + xp[xb + 2 * HH];
        const float ov = gs[b * 64 + 48 + jl] + xp[xb + 3 * HH];

        const float si = 1.f / (1.f + expf(-iv));
        const float sf = 1.f / (1.f + expf(-fv));
        const float tgh = tanhf(gv);
        const float so = 1.f / (1.f + expf(-ov));

        const float cprev = g_c[b * HH + j];
        const float cn = sf * cprev + si * tgh;
        const float hn = so * tanhf(cn);

        g_c[b * HH + j] = cn;
        h_out[b * HH + j] = __float2half_rn(hn);
        ys[(size_t)b * HH + j] = hn;            // raw h; softmax pass later
    }
}

// ===========================================================================
// Kernel 3: in-place row softmax over ys: 16384 rows x 2048
// ===========================================================================
__global__ void __launch_bounds__(256) softmax_kernel(float* __restrict__ out)
{
    const size_t base = (size_t)blockIdx.x * HH;
    const int tid = threadIdx.x;
    const int warp = tid >> 5, lane = tid & 31;
    __shared__ float red[8];

    float v[8];
    #pragma unroll
    for (int i = 0; i < 8; ++i) v[i] = out[base + tid + i * 256];

    float m = v[0];
    #pragma unroll
    for (int i = 1; i < 8; ++i) m = fmaxf(m, v[i]);
    #pragma unroll
    for (int off = 16; off > 0; off >>= 1)
        m = fmaxf(m, __shfl_xor_sync(0xFFFFFFFFu, m, off));
    if (lane == 0) red[warp] = m;
    __syncthreads();
    float bm = red[0];
    #pragma unroll
    for (int i = 1; i < 8; ++i) bm = fmaxf(bm, red[i]);
    __syncthreads();

    float e[8];
    float s = 0.f;
    #pragma unroll
    for (int i = 0; i < 8; ++i) { e[i] = expf(v[i] - bm); s += e[i]; }
    #pragma unroll
    for (int off = 16; off > 0; off >>= 1)
        s += __shfl_xor_sync(0xFFFFFFFFu, s, off);
    if (lane == 0) red[warp] = s;
    __syncthreads();
    float bs = 0.f;
    #pragma unroll
    for (int i = 0; i < 8; ++i) bs += red[i];
    const float inv = 1.f / bs;

    #pragma unroll
    for (int i = 0; i < 8; ++i) out[base + tid + i * 256] = e[i] * inv;
}

// ===========================================================================
// Kernel 4: tail — copy raw h_T (from ys[255], pre-softmax) and c_T
// ===========================================================================
__global__ void tail_kernel(float* __restrict__ out)
{
    const int i = blockIdx.x * blockDim.x + threadIdx.x;
    if (i < BB * HH) {
        out[(size_t)TT * BB * HH + i] = out[(size_t)(TT - 1) * BB * HH + i];
        out[(size_t)TT * BB * HH + BB * HH + i] = g_c[i];
    }
}

// ===========================================================================
extern "C" void kernel_launch(void* const* d_in, const int* in_sizes, int n_in,
                              void* d_out, int out_size)
{
    (void)in_sizes; (void)n_in; (void)out_size;
    const float* input = (const float*)d_in[0];  // [T,B,X]
    const float* h0    = (const float*)d_in[1];  // [B,H]
    const float* c0    = (const float*)d_in[2];  // [B,H]
    const float* wih   = (const float*)d_in[3];  // [4H,X]
    const float* whh   = (const float*)d_in[4];  // [4H,H]
    const float* bih   = (const float*)d_in[5];  // [4H]
    const float* bhh   = (const float*)d_in[6];  // [4H]
    float* out = (float*)d_out;

    // ---- prep ----
    init_state_kernel<<<(BB * HH + 255) / 256, 256>>>(h0, c0);

    {   // input -> fp16 (8,388,608 elems -> 4,194,304 half2)
        __half* dx; cudaGetSymbolAddress((void**)&dx, g_xin);
        conv_f2h_kernel<<<(TT * BB * XX / 2 + 255) / 256, 256>>>(dx, input, TT * BB * XX / 2);
    }
    {   // w_ih -> fp16
        __half* dw; cudaGetSymbolAddress((void**)&dw, g_wih);
        conv_f2h_kernel<<<(G4 * XX / 2 + 255) / 256, 256>>>(dw, wih, G4 * XX / 2);
    }
    reorder_whh_kernel<<<128 * 64, 256>>>(whh);

    // ---- x_proj GEMM ----
    xproj_kernel<<<dim3(G4 / 128, (TT * BB) / 128), 256>>>(bih, bhh);

    // ---- recurrence ----
    for (int t = 0; t < TT; ++t)
        step_kernel<<<HH / 16, 256>>>(t, out);

    // ---- tail (raw h_T) then softmax ----
    tail_kernel<<<(BB * HH + 255) / 256, 256>>>(out);
    softmax_kernel<<<TT * BB, 256>>>(out);
}

// round 5
// speedup vs baseline: 2.2161x; 1.0641x over previous
#include <cuda_runtime.h>
#include <cuda_fp16.h>
#include <cstdint>
#include <math.h>

#define TT 256
#define BB 64
#define XX 512
#define HH 2048
#define G4 8192   // 4*HH
#define NBLK 128  // persistent grid size (<=148 SMs -> single wave)

// ---------------- device scratch (static; no allocations allowed) ----------
__device__ __align__(128) float  g_xproj[(size_t)TT * BB * G4]; // 512 MB
__device__ __align__(128) __half g_hh[2][BB * HH];              // fp16 hidden ping-pong
__device__ __align__(128) float  g_c[BB * HH];                  // final cell state
__device__ __align__(128) __half g_Wp[(size_t)G4 * HH];         // reordered fp16 W_hh (32 MB)
__device__ __align__(128) __half g_xin[(size_t)TT * BB * XX];   // fp16 input
__device__ __align__(128) __half g_wih[(size_t)G4 * XX];        // fp16 w_ih
__device__ unsigned g_bar;                                      // grid barrier counter

// ---------------- PTX helpers ----------------------------------------------
__device__ __forceinline__ void mma16(float* d, const uint32_t* a, const uint32_t* b) {
    asm volatile(
        "mma.sync.aligned.m16n8k16.row.col.f32.f16.f16.f32 "
        "{%0,%1,%2,%3},{%4,%5,%6,%7},{%8,%9},{%0,%1,%2,%3};"
        : "+f"(d[0]), "+f"(d[1]), "+f"(d[2]), "+f"(d[3])
        : "r"(a[0]), "r"(a[1]), "r"(a[2]), "r"(a[3]), "r"(b[0]), "r"(b[1]));
}

__device__ __forceinline__ void cpa16_ca(uint32_t smem_addr, const void* gptr) {
    asm volatile("cp.async.ca.shared.global [%0], [%1], 16;"
                 :: "r"(smem_addr), "l"(gptr));
}
__device__ __forceinline__ void cpa16_cg(uint32_t smem_addr, const void* gptr) {
    asm volatile("cp.async.cg.shared.global [%0], [%1], 16;"
                 :: "r"(smem_addr), "l"(gptr));
}
__device__ __forceinline__ void cp_commit() { asm volatile("cp.async.commit_group;"); }
template <int N>
__device__ __forceinline__ void cp_wait() { asm volatile("cp.async.wait_group %0;" :: "n"(N)); }

// ===========================================================================
// Prep kernels
// ===========================================================================
__global__ void init_state_kernel(const float* __restrict__ h0)
{
    const int i = blockIdx.x * blockDim.x + threadIdx.x;
    if (i == 0) g_bar = 0;                    // reset grid barrier each replay
    if (i < BB * HH)
        g_hh[1][i] = __float2half_rn(h0[i]);  // step t=0 reads g_hh[1]
}

__global__ void conv_f2h_kernel(__half* __restrict__ dst,
                                const float* __restrict__ src, int n2)
{
    const int i = blockIdx.x * blockDim.x + threadIdx.x;
    if (i < n2) {
        float2 v = ((const float2*)src)[i];
        ((__half2*)dst)[i] = __float22half2_rn(v);
    }
}

// Reorder W_hh [8192,2048] fp32 -> g_Wp fp16:
//   g_Wp[ ((jb*64 + chunk)*64 + r)*32 + kin ],
//   local row r -> global row (r>>4)*HH + jb*16 + (r&15); chunk = k0/32.
__global__ void __launch_bounds__(256) reorder_whh_kernel(const float* __restrict__ W)
{
    const int bx = blockIdx.x;           // jb*64 + chunk
    const int jb = bx >> 6, chunk = bx & 63;
    const int tid = threadIdx.x;
    const int r = tid >> 2, kq = tid & 3;
    const int kin = kq * 8;
    const int grow = (r >> 4) * HH + jb * 16 + (r & 15);
    const float* s = W + (size_t)grow * HH + chunk * 32 + kin;
    float4 v0 = *(const float4*)s;
    float4 v1 = *(const float4*)(s + 4);
    __half2 h[4];
    h[0] = __float22half2_rn(make_float2(v0.x, v0.y));
    h[1] = __float22half2_rn(make_float2(v0.z, v0.w));
    h[2] = __float22half2_rn(make_float2(v1.x, v1.y));
    h[3] = __float22half2_rn(make_float2(v1.z, v1.w));
    *(uint4*)(g_Wp + ((size_t)bx * 64 + r) * 32 + kin) = *(uint4*)h;
}

// ===========================================================================
// Kernel 1: x_proj = input @ w_ih^T + b_ih + b_hh   (fp16 MMA, 128x128 tiles)
// ===========================================================================
__global__ void __launch_bounds__(256) xproj_kernel(
    const float* __restrict__ bih, const float* __restrict__ bhh)
{
    __shared__ __align__(16) __half sm[2][2][128 * 40];

    const int tid = threadIdx.x;
    const int m0 = blockIdx.y * 128;
    const int n0 = blockIdx.x * 128;
    const int warp = tid >> 5, lane = tid & 31;
    const int wm = warp & 3, wn = warp >> 2;
    const int g = lane >> 2, tg = lane & 3;

    float acc[2][8][4];
    #pragma unroll
    for (int a = 0; a < 2; ++a)
        #pragma unroll
        for (int b = 0; b < 8; ++b)
            #pragma unroll
            for (int c = 0; c < 4; ++c) acc[a][b][c] = 0.f;

    const __half* A = g_xin;
    const __half* B = g_wih;
    const int NCH = XX / 32;

    auto issue = [&](int ch) {
        const int st = ch & 1;
        const int k0 = ch * 32;
        #pragma unroll
        for (int rep = 0; rep < 2; ++rep) {
            const int q = tid + rep * 256;
            const int r = q >> 2, kq = q & 3;
            cpa16_ca((uint32_t)__cvta_generic_to_shared(&sm[st][0][r * 40 + kq * 8]),
                     A + (size_t)(m0 + r) * XX + k0 + kq * 8);
            cpa16_ca((uint32_t)__cvta_generic_to_shared(&sm[st][1][r * 40 + kq * 8]),
                     B + (size_t)(n0 + r) * XX + k0 + kq * 8);
        }
    };

    issue(0); cp_commit();

    for (int ch = 0; ch < NCH; ++ch) {
        if (ch + 1 < NCH) issue(ch + 1);
        cp_commit();
        cp_wait<1>();
        __syncthreads();

        const __half* As = sm[ch & 1][0];
        const __half* Bs = sm[ch & 1][1];
        #pragma unroll
        for (int kk = 0; kk < 32; kk += 16) {
            #pragma unroll
            for (int mt = 0; mt < 2; ++mt) {
                uint32_t af[4];
                const int mr = wm * 32 + mt * 16 + g;
                af[0] = *(const uint32_t*)&As[mr * 40 + kk + tg * 2];
                af[1] = *(const uint32_t*)&As[(mr + 8) * 40 + kk + tg * 2];
                af[2] = *(const uint32_t*)&As[mr * 40 + kk + tg * 2 + 8];
                af[3] = *(const uint32_t*)&As[(mr + 8) * 40 + kk + tg * 2 + 8];
                #pragma unroll
                for (int nt = 0; nt < 8; ++nt) {
                    uint32_t bf[2];
                    const int nr = wn * 64 + nt * 8 + g;
                    bf[0] = *(const uint32_t*)&Bs[nr * 40 + kk + tg * 2];
                    bf[1] = *(const uint32_t*)&Bs[nr * 40 + kk + tg * 2 + 8];
                    mma16(acc[mt][nt], af, bf);
                }
            }
        }
        __syncthreads();
    }

    #pragma unroll
    for (int mt = 0; mt < 2; ++mt) {
        #pragma unroll
        for (int nt = 0; nt < 8; ++nt) {
            const int col = n0 + wn * 64 + nt * 8 + tg * 2;
            const float b0 = bih[col] + bhh[col];
            const float b1 = bih[col + 1] + bhh[col + 1];
            const int row = m0 + wm * 32 + mt * 16 + g;
            g_xproj[(size_t)row * G4 + col]           = acc[mt][nt][0] + b0;
            g_xproj[(size_t)row * G4 + col + 1]       = acc[mt][nt][1] + b1;
            g_xproj[(size_t)(row + 8) * G4 + col]     = acc[mt][nt][2] + b0;
            g_xproj[(size_t)(row + 8) * G4 + col + 1] = acc[mt][nt][3] + b1;
        }
    }
}

// ===========================================================================
// Kernel 2: PERSISTENT recurrence. 128 blocks, all 256 steps, grid barrier
// between steps. Block jb owns 16 hidden units x 4 gates; c in registers.
// ===========================================================================
__global__ void __launch_bounds__(256) recur_kernel(
    const float* __restrict__ c0, float* __restrict__ out)
{
    __shared__ __align__(16) __half sm[4][2][64 * 40];   // 40,960 B

    const int tid = threadIdx.x;
    const int jb = blockIdx.x;
    const int j0 = jb * 16;
    const int warp = tid >> 5, lane = tid & 31;
    const int wm = warp & 3, wn = warp >> 2;
    const int g = lane >> 2, tg = lane & 3;
    const int m_base = wm * 16, n_base = wn * 32;
    const __half* __restrict__ Wb = g_Wp + (size_t)jb * 64 * HH;
    const int r = tid >> 2, kq = tid & 3;
    const int NCH = HH / 32;   // 64

    // per-thread elementwise lanes: items idx = tid + it*256
    int eb[4], ej[4];
    #pragma unroll
    for (int it = 0; it < 4; ++it) {
        const int idx = tid + it * 256;
        eb[it] = idx >> 4;
        ej[it] = idx & 15;
    }

    // cell state lives in registers for the whole sequence
    float creg[4];
    #pragma unroll
    for (int it = 0; it < 4; ++it)
        creg[it] = c0[eb[it] * HH + j0 + ej[it]];

    for (int t = 0; t < TT; ++t) {
        const __half* __restrict__ h_in = g_hh[(t + 1) & 1];
        __half* __restrict__ h_out = g_hh[t & 1];
        float* __restrict__ ys = out + (size_t)t * BB * HH;
        const float* __restrict__ xp = g_xproj + (size_t)t * BB * G4;

        // prefetch x_proj gate values into registers (hidden behind GEMM)
        float xr[4][4];
        #pragma unroll
        for (int it = 0; it < 4; ++it) {
            const size_t xb = (size_t)eb[it] * G4 + j0 + ej[it];
            xr[it][0] = __ldg(xp + xb);
            xr[it][1] = __ldg(xp + xb + HH);
            xr[it][2] = __ldg(xp + xb + 2 * HH);
            xr[it][3] = __ldg(xp + xb + 3 * HH);
        }

        float acc[4][4];
        #pragma unroll
        for (int i = 0; i < 4; ++i)
            #pragma unroll
            for (int j = 0; j < 4; ++j) acc[i][j] = 0.f;

        auto issue = [&](int ch) {
            const int st = ch & 3;
            const int k0 = ch * 32;
            // h: L2-only (must see other SMs' writes; L1 persists in this kernel)
            cpa16_cg((uint32_t)__cvta_generic_to_shared(&sm[st][0][r * 40 + kq * 8]),
                     h_in + (size_t)r * HH + k0 + kq * 8);
            // W: immutable, let it live in L1 across steps
            cpa16_ca((uint32_t)__cvta_generic_to_shared(&sm[st][1][r * 40 + kq * 8]),
                     Wb + ((size_t)ch * 64 + r) * 32 + kq * 8);
        };

        issue(0); cp_commit();
        issue(1); cp_commit();
        issue(2); cp_commit();

        for (int ch = 0; ch < NCH; ++ch) {
            cp_wait<2>();
            __syncthreads();

            const __half* As = sm[ch & 3][0];
            const __half* Bs = sm[ch & 3][1];
            #pragma unroll
            for (int kk = 0; kk < 32; kk += 16) {
                uint32_t af[4];
                af[0] = *(const uint32_t*)&As[(m_base + g) * 40 + kk + tg * 2];
                af[1] = *(const uint32_t*)&As[(m_base + g + 8) * 40 + kk + tg * 2];
                af[2] = *(const uint32_t*)&As[(m_base + g) * 40 + kk + tg * 2 + 8];
                af[3] = *(const uint32_t*)&As[(m_base + g + 8) * 40 + kk + tg * 2 + 8];
                #pragma unroll
                for (int nt = 0; nt < 4; ++nt) {
                    uint32_t bf[2];
                    const int nr = n_base + nt * 8 + g;
                    bf[0] = *(const uint32_t*)&Bs[nr * 40 + kk + tg * 2];
                    bf[1] = *(const uint32_t*)&Bs[nr * 40 + kk + tg * 2 + 8];
                    mma16(acc[nt], af, bf);
                }
            }

            if (ch + 3 < NCH) issue(ch + 3);
            cp_commit();   // keep wait<2> bookkeeping exact
        }

        cp_wait<0>();
        __syncthreads();

        // stage gates into smem (alias pipeline buffers)
        float* gs = (float*)&sm[0][0][0];
        #pragma unroll
        for (int nt = 0; nt < 4; ++nt) {
            const int col = n_base + nt * 8 + tg * 2;
            const int row = m_base + g;
            gs[row * 64 + col]           = acc[nt][0];
            gs[row * 64 + col + 1]       = acc[nt][1];
            gs[(row + 8) * 64 + col]     = acc[nt][2];
            gs[(row + 8) * 64 + col + 1] = acc[nt][3];
        }
        __syncthreads();

        // fused elementwise LSTM update
        #pragma unroll
        for (int it = 0; it < 4; ++it) {
            const int b = eb[it], jl = ej[it];
            const int j = j0 + jl;
            const float iv = gs[b * 64 + jl]      + xr[it][0];
            const float fv = gs[b * 64 + 16 + jl] + xr[it][1];
            const float gv = gs[b * 64 + 32 + jl] + xr[it][2];
            const float ov = gs[b * 64 + 48 + jl] + xr[it][3];

            const float si = 1.f / (1.f + expf(-iv));
            const float sf = 1.f / (1.f + expf(-fv));
            const float tgh = tanhf(gv);
            const float so = 1.f / (1.f + expf(-ov));

            const float cn = sf * creg[it] + si * tgh;
            const float hn = so * tanhf(cn);
            creg[it] = cn;

            h_out[b * HH + j] = __float2half_rn(hn);
            ys[(size_t)b * HH + j] = hn;
            if (t == TT - 1) g_c[b * HH + j] = cn;
        }

        // ---- grid barrier ----
        __syncthreads();
        if (tid == 0) {
            __threadfence();
            atomicAdd(&g_bar, 1u);
            const unsigned target = (unsigned)(t + 1) * NBLK;
            unsigned v;
            do {
                asm volatile("ld.acquire.gpu.u32 %0, [%1];" : "=r"(v) : "l"(&g_bar));
                if (v < target) __nanosleep(32);
            } while (v < target);
        }
        __syncthreads();
    }
}

// ===========================================================================
// Kernel 3: in-place row softmax over ys: 16384 rows x 2048
// ===========================================================================
__global__ void __launch_bounds__(256) softmax_kernel(float* __restrict__ out)
{
    const size_t base = (size_t)blockIdx.x * HH;
    const int tid = threadIdx.x;
    const int warp = tid >> 5, lane = tid & 31;
    __shared__ float red[8];

    float v[8];
    #pragma unroll
    for (int i = 0; i < 8; ++i) v[i] = out[base + tid + i * 256];

    float m = v[0];
    #pragma unroll
    for (int i = 1; i < 8; ++i) m = fmaxf(m, v[i]);
    #pragma unroll
    for (int off = 16; off > 0; off >>= 1)
        m = fmaxf(m, __shfl_xor_sync(0xFFFFFFFFu, m, off));
    if (lane == 0) red[warp] = m;
    __syncthreads();
    float bm = red[0];
    #pragma unroll
    for (int i = 1; i < 8; ++i) bm = fmaxf(bm, red[i]);
    __syncthreads();

    float e[8];
    float s = 0.f;
    #pragma unroll
    for (int i = 0; i < 8; ++i) { e[i] = expf(v[i] - bm); s += e[i]; }
    #pragma unroll
    for (int off = 16; off > 0; off >>= 1)
        s += __shfl_xor_sync(0xFFFFFFFFu, s, off);
    if (lane == 0) red[warp] = s;
    __syncthreads();
    float bs = 0.f;
    #pragma unroll
    for (int i = 0; i < 8; ++i) bs += red[i];
    const float inv = 1.f / bs;

    #pragma unroll
    for (int i = 0; i < 8; ++i) out[base + tid + i * 256] = e[i] * inv;
}

// ===========================================================================
// Kernel 4: tail — copy raw h_T (pre-softmax ys[255]) and c_T
// ===========================================================================
__global__ void tail_kernel(float* __restrict__ out)
{
    const int i = blockIdx.x * blockDim.x + threadIdx.x;
    if (i < BB * HH) {
        out[(size_t)TT * BB * HH + i] = out[(size_t)(TT - 1) * BB * HH + i];
        out[(size_t)TT * BB * HH + BB * HH + i] = g_c[i];
    }
}

// ===========================================================================
extern "C" void kernel_launch(void* const* d_in, const int* in_sizes, int n_in,
                              void* d_out, int out_size)
{
    (void)in_sizes; (void)n_in; (void)out_size;
    const float* input = (const float*)d_in[0];
    const float* h0    = (const float*)d_in[1];
    const float* c0    = (const float*)d_in[2];
    const float* wih   = (const float*)d_in[3];
    const float* whh   = (const float*)d_in[4];
    const float* bih   = (const float*)d_in[5];
    const float* bhh   = (const float*)d_in[6];
    float* out = (float*)d_out;

    // ---- prep ----
    init_state_kernel<<<(BB * HH + 255) / 256, 256>>>(h0);

    {
        __half* dx; cudaGetSymbolAddress((void**)&dx, g_xin);
        conv_f2h_kernel<<<(TT * BB * XX / 2 + 255) / 256, 256>>>(dx, input, TT * BB * XX / 2);
    }
    {
        __half* dw; cudaGetSymbolAddress((void**)&dw, g_wih);
        conv_f2h_kernel<<<(G4 * XX / 2 + 255) / 256, 256>>>(dw, wih, G4 * XX / 2);
    }
    reorder_whh_kernel<<<128 * 64, 256>>>(whh);

    // ---- x_proj GEMM ----
    xproj_kernel<<<dim3(G4 / 128, (TT * BB) / 128), 256>>>(bih, bhh);

    // ---- persistent recurrence (all 256 steps) ----
    recur_kernel<<<NBLK, 256>>>(c0, out);

    // ---- tail (raw h_T) then softmax ----
    tail_kernel<<<(BB * HH + 255) / 256, 256>>>(out);
    softmax_kernel<<<TT * BB, 256>>>(out);
}

// round 8
// speedup vs baseline: 2.6522x; 1.1968x over previous
#include <cuda_runtime.h>
#include <cuda_fp16.h>
#include <cstdint>
#include <math.h>

#define TT 256
#define BB 64
#define XX 512
#define HH 2048
#define G4 8192   // 4*HH
#define NBLK 128  // persistent grid size (single wave, <=148 SMs)

#define CHK 64               // K per chunk in recurrence
#define NCH 32               // 2048 / 64
#define SRES 16              // W chunks resident in SMEM
#define LDH 72               // smem leading dim (halfs): 144B row stride -> ldmatrix conflict-free
#define TILEH (64 * LDH)     // halfs per 64-row tile = 4608
#define DSMEM_BYTES ((SRES + 8) * TILEH * 2)   // 221,184 B (< 227 KB opt-in)

// ---------------- device scratch (static; no allocations allowed) ----------
__device__ __align__(128) float  g_xproj[(size_t)TT * BB * G4]; // 512 MB
__device__ __align__(128) __half g_hh[2][BB * HH];              // fp16 hidden ping-pong
__device__ __align__(128) float  g_c[BB * HH];                  // final cell state
__device__ __align__(128) __half g_Wp[(size_t)G4 * HH];         // reordered fp16 W_hh (32 MB)
__device__ __align__(128) __half g_xin[(size_t)TT * BB * XX];   // fp16 input
__device__ __align__(128) __half g_wih[(size_t)G4 * XX];        // fp16 w_ih
__device__ unsigned g_bar;                                      // grid barrier counter

// ---------------- PTX helpers ----------------------------------------------
__device__ __forceinline__ void mma16(float* d, const uint32_t* a, uint32_t b0, uint32_t b1) {
    asm volatile(
        "mma.sync.aligned.m16n8k16.row.col.f32.f16.f16.f32 "
        "{%0,%1,%2,%3},{%4,%5,%6,%7},{%8,%9},{%0,%1,%2,%3};"
        : "+f"(d[0]), "+f"(d[1]), "+f"(d[2]), "+f"(d[3])
        : "r"(a[0]), "r"(a[1]), "r"(a[2]), "r"(a[3]), "r"(b0), "r"(b1));
}

__device__ __forceinline__ void ldsm4(uint32_t* r, const void* p) {
    uint32_t a = (uint32_t)__cvta_generic_to_shared(p);
    asm volatile("ldmatrix.sync.aligned.m8n8.x4.shared.b16 {%0,%1,%2,%3}, [%4];"
                 : "=r"(r[0]), "=r"(r[1]), "=r"(r[2]), "=r"(r[3]) : "r"(a));
}

__device__ __forceinline__ void cpa16_ca(const void* smem, const void* gptr) {
    uint32_t a = (uint32_t)__cvta_generic_to_shared(smem);
    asm volatile("cp.async.ca.shared.global [%0], [%1], 16;" :: "r"(a), "l"(gptr));
}
__device__ __forceinline__ void cpa16_cg(const void* smem, const void* gptr) {
    uint32_t a = (uint32_t)__cvta_generic_to_shared(smem);
    asm volatile("cp.async.cg.shared.global [%0], [%1], 16;" :: "r"(a), "l"(gptr));
}
__device__ __forceinline__ void cp_commit() { asm volatile("cp.async.commit_group;"); }
template <int N>
__device__ __forceinline__ void cp_wait() { asm volatile("cp.async.wait_group %0;" :: "n"(N)); }

// ===========================================================================
// Prep kernels
// ===========================================================================
__global__ void init_state_kernel(const float* __restrict__ h0)
{
    const int i = blockIdx.x * blockDim.x + threadIdx.x;
    if (i == 0) g_bar = 0;                    // reset grid barrier each replay
    if (i < BB * HH)
        g_hh[1][i] = __float2half_rn(h0[i]);  // step t=0 reads g_hh[1]
}

__global__ void conv_f2h_kernel(__half* __restrict__ dst,
                                const float* __restrict__ src, int n2)
{
    const int i = blockIdx.x * blockDim.x + threadIdx.x;
    if (i < n2) {
        float2 v = ((const float2*)src)[i];
        ((__half2*)dst)[i] = __float22half2_rn(v);
    }
}

// Reorder W_hh [8192,2048] fp32 -> g_Wp fp16, chunked layout:
//   g_Wp[ ((jb*NCH + ch)*64 + r)*64 + k ]   (k within chunk, dense 64)
// local row r -> global gate row (r>>4)*HH + jb*16 + (r&15).
__global__ void __launch_bounds__(256) reorder_whh_kernel(const float* __restrict__ W)
{
    const int bx = blockIdx.x;           // jb*NCH + ch   (grid = 128*32)
    const int jb = bx >> 5, ch = bx & 31;
    const int tid = threadIdx.x;
    const int r = tid >> 2;              // 0..63
    const int q = tid & 3;               // 16-half segment
    const int grow = (r >> 4) * HH + jb * 16 + (r & 15);
    const float* s = W + (size_t)grow * HH + ch * CHK + q * 16;

    __half hb[16];
    #pragma unroll
    for (int i = 0; i < 16; i += 4) {
        float4 v = *(const float4*)(s + i);
        hb[i + 0] = __float2half_rn(v.x);
        hb[i + 1] = __float2half_rn(v.y);
        hb[i + 2] = __float2half_rn(v.z);
        hb[i + 3] = __float2half_rn(v.w);
    }
    __half* d = g_Wp + ((size_t)bx * 64 + r) * 64 + q * 16;
    *(uint4*)d = *(uint4*)hb;
    *(uint4*)(d + 8) = *(uint4*)(hb + 8);
}

// ===========================================================================
// Kernel 1: x_proj = input @ w_ih^T + b_ih + b_hh   (fp16 MMA, 128x128 tiles)
// ===========================================================================
__global__ void __launch_bounds__(256) xproj_kernel(
    const float* __restrict__ bih, const float* __restrict__ bhh)
{
    __shared__ __align__(16) __half sm[2][2][128 * 40];

    const int tid = threadIdx.x;
    const int m0 = blockIdx.y * 128;
    const int n0 = blockIdx.x * 128;
    const int warp = tid >> 5, lane = tid & 31;
    const int wm = warp & 3, wn = warp >> 2;
    const int g = lane >> 2, tg = lane & 3;

    float acc[2][8][4];
    #pragma unroll
    for (int a = 0; a < 2; ++a)
        #pragma unroll
        for (int b = 0; b < 8; ++b)
            #pragma unroll
            for (int c = 0; c < 4; ++c) acc[a][b][c] = 0.f;

    const __half* A = g_xin;
    const __half* B = g_wih;
    const int NC = XX / 32;

    auto issue = [&](int ch) {
        const int st = ch & 1;
        const int k0 = ch * 32;
        #pragma unroll
        for (int rep = 0; rep < 2; ++rep) {
            const int q = tid + rep * 256;
            const int r = q >> 2, kq = q & 3;
            cpa16_ca(&sm[st][0][r * 40 + kq * 8], A + (size_t)(m0 + r) * XX + k0 + kq * 8);
            cpa16_ca(&sm[st][1][r * 40 + kq * 8], B + (size_t)(n0 + r) * XX + k0 + kq * 8);
        }
    };

    issue(0); cp_commit();

    for (int ch = 0; ch < NC; ++ch) {
        if (ch + 1 < NC) issue(ch + 1);
        cp_commit();
        cp_wait<1>();
        __syncthreads();

        const __half* As = sm[ch & 1][0];
        const __half* Bs = sm[ch & 1][1];
        #pragma unroll
        for (int kk = 0; kk < 32; kk += 16) {
            #pragma unroll
            for (int mt = 0; mt < 2; ++mt) {
                uint32_t af[4];
                const int mr = wm * 32 + mt * 16 + g;
                af[0] = *(const uint32_t*)&As[mr * 40 + kk + tg * 2];
                af[1] = *(const uint32_t*)&As[(mr + 8) * 40 + kk + tg * 2];
                af[2] = *(const uint32_t*)&As[mr * 40 + kk + tg * 2 + 8];
                af[3] = *(const uint32_t*)&As[(mr + 8) * 40 + kk + tg * 2 + 8];
                #pragma unroll
                for (int nt = 0; nt < 8; ++nt) {
                    const int nr = wn * 64 + nt * 8 + g;
                    mma16(acc[mt][nt], af,
                          *(const uint32_t*)&Bs[nr * 40 + kk + tg * 2],
                          *(const uint32_t*)&Bs[nr * 40 + kk + tg * 2 + 8]);
                }
            }
        }
        __syncthreads();
    }

    #pragma unroll
    for (int mt = 0; mt < 2; ++mt) {
        #pragma unroll
        for (int nt = 0; nt < 8; ++nt) {
            const int col = n0 + wn * 64 + nt * 8 + tg * 2;
            const float b0 = bih[col] + bhh[col];
            const float b1 = bih[col + 1] + bhh[col + 1];
            const int row = m0 + wm * 32 + mt * 16 + g;
            g_xproj[(size_t)row * G4 + col]           = acc[mt][nt][0] + b0;
            g_xproj[(size_t)row * G4 + col + 1]       = acc[mt][nt][1] + b1;
            g_xproj[(size_t)(row + 8) * G4 + col]     = acc[mt][nt][2] + b0;
            g_xproj[(size_t)(row + 8) * G4 + col + 1] = acc[mt][nt][3] + b1;
        }
    }
}

// ===========================================================================
// Kernel 2: PERSISTENT recurrence. 128 blocks, all 256 steps, grid barrier.
// Block jb owns 16 hidden units x 4 gates (64 gate cols), all 64 batches.
// 16/32 W chunks live in SMEM for the whole kernel; ldmatrix operand loads.
// ===========================================================================
extern __shared__ __align__(16) __half ds[];

__global__ void __launch_bounds__(256) recur_kernel(
    const float* __restrict__ c0, float* __restrict__ out)
{
    __half* Wres = ds;                         // SRES * TILEH  (144 KB)
    __half* hstg = ds + SRES * TILEH;          // 4 * TILEH     (36 KB ring)
    __half* Wstg = hstg + 4 * TILEH;           // 4 * TILEH     (36 KB ring)
    float*  gs   = (float*)hstg;               // epilogue alias (16 KB)

    const int tid = threadIdx.x;
    const int jb = blockIdx.x;
    const int j0 = jb * 16;
    const int warp = tid >> 5, lane = tid & 31;
    const int wm = warp & 3, wn = warp >> 2;           // 4m x 2n warps
    const int g = lane >> 2, tg = lane & 3;
    const int m_base = wm * 16, n_base = wn * 32;
    const int quad = lane >> 3, rin = lane & 7;
    const int arow = m_base + rin + ((quad & 1) << 3);   // ldmatrix addr row (A)
    const int brow = n_base + rin + ((quad & 1) << 3);   // ldmatrix addr row (B)
    const int koff = (quad >> 1) << 3;                   // ldmatrix k sub-offset

    const __half* __restrict__ Wb = g_Wp + (size_t)jb * (NCH * 64 * 64);

    // ---- preload resident W chunks into SMEM (once) ----
    for (int s = tid; s < SRES * 512; s += 256) {
        const int chk = s >> 9, seg = s & 511;
        const int r = seg >> 3, ks = seg & 7;
        cpa16_ca(&Wres[chk * TILEH + r * LDH + ks * 8],
                 Wb + ((size_t)chk * 64 + r) * 64 + ks * 8);
    }
    cp_commit(); cp_wait<0>(); __syncthreads();

    // per-thread elementwise lanes
    int eb[4], ej[4];
    #pragma unroll
    for (int it = 0; it < 4; ++it) {
        const int idx = tid + it * 256;
        eb[it] = idx >> 4;
        ej[it] = idx & 15;
    }
    float creg[4];
    #pragma unroll
    for (int it = 0; it < 4; ++it)
        creg[it] = c0[eb[it] * HH + j0 + ej[it]];

    for (int t = 0; t < TT; ++t) {
        const __half* __restrict__ h_in = g_hh[(t + 1) & 1];
        __half* __restrict__ h_out = g_hh[t & 1];
        float* __restrict__ ys = out + (size_t)t * BB * HH;
        const float* __restrict__ xp = g_xproj + (size_t)t * BB * G4;

        // prefetch x_proj gate values (consumed at epilogue)
        float xr[4][4];
        #pragma unroll
        for (int it = 0; it < 4; ++it) {
            const size_t xb = (size_t)eb[it] * G4 + j0 + ej[it];
            xr[it][0] = __ldg(xp + xb);
            xr[it][1] = __ldg(xp + xb + HH);
            xr[it][2] = __ldg(xp + xb + 2 * HH);
            xr[it][3] = __ldg(xp + xb + 3 * HH);
        }

        float acc[4][4];
        #pragma unroll
        for (int i = 0; i < 4; ++i)
            #pragma unroll
            for (int j = 0; j < 4; ++j) acc[i][j] = 0.f;

        auto issue = [&](int ch) {
            const int st = ch & 3;
            #pragma unroll
            for (int i = 0; i < 2; ++i) {
                const int s = tid + i * 256;
                const int r = s >> 3, ks = s & 7;
                cpa16_cg(&hstg[st * TILEH + r * LDH + ks * 8],
                         h_in + (size_t)r * HH + ch * CHK + ks * 8);
            }
            if (ch >= SRES) {
                #pragma unroll
                for (int i = 0; i < 2; ++i) {
                    const int s = tid + i * 256;
                    const int r = s >> 3, ks = s & 7;
                    cpa16_ca(&Wstg[st * TILEH + r * LDH + ks * 8],
                             Wb + ((size_t)ch * 64 + r) * 64 + ks * 8);
                }
            }
        };

        issue(0); cp_commit();
        issue(1); cp_commit();
        issue(2); cp_commit();

        for (int ch = 0; ch < NCH; ++ch) {
            cp_wait<2>();
            __syncthreads();

            const __half* As = &hstg[(ch & 3) * TILEH];
            const __half* Bs = (ch < SRES) ? &Wres[ch * TILEH]
                                           : &Wstg[(ch & 3) * TILEH];
            #pragma unroll
            for (int kk = 0; kk < CHK; kk += 16) {
                uint32_t a[4], b0[4], b1[4];
                ldsm4(a,  &As[arow * LDH + kk + koff]);
                ldsm4(b0, &Bs[brow * LDH + kk + koff]);
                ldsm4(b1, &Bs[(brow + 16) * LDH + kk + koff]);
                mma16(acc[0], a, b0[0], b0[2]);
                mma16(acc[1], a, b0[1], b0[3]);
                mma16(acc[2], a, b1[0], b1[2]);
                mma16(acc[3], a, b1[1], b1[3]);
            }

            if (ch + 3 < NCH) issue(ch + 3);
            cp_commit();   // keep wait<2> bookkeeping exact
        }

        cp_wait<0>();
        __syncthreads();

        // stage gates into smem (alias h ring)
        #pragma unroll
        for (int nt = 0; nt < 4; ++nt) {
            const int col = n_base + nt * 8 + tg * 2;
            const int row = m_base + g;
            gs[row * 64 + col]           = acc[nt][0];
            gs[row * 64 + col + 1]       = acc[nt][1];
            gs[(row + 8) * 64 + col]     = acc[nt][2];
            gs[(row + 8) * 64 + col + 1] = acc[nt][3];
        }
        __syncthreads();

        // fused elementwise LSTM update
        #pragma unroll
        for (int it = 0; it < 4; ++it) {
            const int b = eb[it], jl = ej[it];
            const int j = j0 + jl;
            const float iv = gs[b * 64 + jl]      + xr[it][0];
            const float fv = gs[b * 64 + 16 + jl] + xr[it][1];
            const float gv = gs[b * 64 + 32 + jl] + xr[it][2];
            const float ov = gs[b * 64 + 48 + jl] + xr[it][3];

            const float si = 1.f / (1.f + expf(-iv));
            const float sf = 1.f / (1.f + expf(-fv));
            const float tgh = tanhf(gv);
            const float so = 1.f / (1.f + expf(-ov));

            const float cn = sf * creg[it] + si * tgh;
            const float hn = so * tanhf(cn);
            creg[it] = cn;

            h_out[b * HH + j] = __float2half_rn(hn);
            ys[(size_t)b * HH + j] = hn;
            if (t == TT - 1) g_c[b * HH + j] = cn;
        }

        // ---- grid barrier (bounded spin: a latent bug surfaces as a wrong
        //      answer instead of a container-killing timeout) ----
        __syncthreads();
        if (tid == 0) {
            __threadfence();
            atomicAdd(&g_bar, 1u);
            const unsigned target = (unsigned)(t + 1) * NBLK;
            unsigned v;
            unsigned spins = 0;
            do {
                asm volatile("ld.acquire.gpu.u32 %0, [%1];" : "=r"(v) : "l"(&g_bar));
                if (v < target) {
                    __nanosleep(32);
                    if (++spins > (1u << 20)) break;   // ~0.1 s cap; never hit normally
                }
            } while (v < target);
        }
        __syncthreads();
    }
}

// ===========================================================================
// Kernel 3: in-place row softmax over ys: 16384 rows x 2048
// ===========================================================================
__global__ void __launch_bounds__(256) softmax_kernel(float* __restrict__ out)
{
    const size_t base = (size_t)blockIdx.x * HH;
    const int tid = threadIdx.x;
    const int warp = tid >> 5, lane = tid & 31;
    __shared__ float red[8];

    float v[8];
    #pragma unroll
    for (int i = 0; i < 8; ++i) v[i] = out[base + tid + i * 256];

    float m = v[0];
    #pragma unroll
    for (int i = 1; i < 8; ++i) m = fmaxf(m, v[i]);
    #pragma unroll
    for (int off = 16; off > 0; off >>= 1)
        m = fmaxf(m, __shfl_xor_sync(0xFFFFFFFFu, m, off));
    if (lane == 0) red[warp] = m;
    __syncthreads();
    float bm = red[0];
    #pragma unroll
    for (int i = 1; i < 8; ++i) bm = fmaxf(bm, red[i]);
    __syncthreads();

    float e[8];
    float s = 0.f;
    #pragma unroll
    for (int i = 0; i < 8; ++i) { e[i] = expf(v[i] - bm); s += e[i]; }
    #pragma unroll
    for (int off = 16; off > 0; off >>= 1)
        s += __shfl_xor_sync(0xFFFFFFFFu, s, off);
    if (lane == 0) red[warp] = s;
    __syncthreads();
    float bs = 0.f;
    #pragma unroll
    for (int i = 0; i < 8; ++i) bs += red[i];
    const float inv = 1.f / bs;

    #pragma unroll
    for (int i = 0; i < 8; ++i) out[base + tid + i * 256] = e[i] * inv;
}

// ===========================================================================
// Kernel 4: tail — copy raw h_T (pre-softmax ys[255]) and c_T
// ===========================================================================
__global__ void tail_kernel(float* __restrict__ out)
{
    const int i = blockIdx.x * blockDim.x + threadIdx.x;
    if (i < BB * HH) {
        out[(size_t)TT * BB * HH + i] = out[(size_t)(TT - 1) * BB * HH + i];
        out[(size_t)TT * BB * HH + BB * HH + i] = g_c[i];
    }
}

// ===========================================================================
extern "C" void kernel_launch(void* const* d_in, const int* in_sizes, int n_in,
                              void* d_out, int out_size)
{
    (void)in_sizes; (void)n_in; (void)out_size;
    const float* input = (const float*)d_in[0];
    const float* h0    = (const float*)d_in[1];
    const float* c0    = (const float*)d_in[2];
    const float* wih   = (const float*)d_in[3];
    const float* whh   = (const float*)d_in[4];
    const float* bih   = (const float*)d_in[5];
    const float* bhh   = (const float*)d_in[6];
    float* out = (float*)d_out;

    // Idempotent, capture-safe; called every invocation (no static guards).
    cudaFuncSetAttribute(recur_kernel,
                         cudaFuncAttributeMaxDynamicSharedMemorySize,
                         DSMEM_BYTES);

    // ---- prep ----
    init_state_kernel<<<(BB * HH + 255) / 256, 256>>>(h0);

    {
        __half* dx; cudaGetSymbolAddress((void**)&dx, g_xin);
        conv_f2h_kernel<<<(TT * BB * XX / 2 + 255) / 256, 256>>>(dx, input, TT * BB * XX / 2);
    }
    {
        __half* dw; cudaGetSymbolAddress((void**)&dw, g_wih);
        conv_f2h_kernel<<<(G4 * XX / 2 + 255) / 256, 256>>>(dw, wih, G4 * XX / 2);
    }
    reorder_whh_kernel<<<128 * 32, 256>>>(whh);

    // ---- x_proj GEMM ----
    xproj_kernel<<<dim3(G4 / 128, (TT * BB) / 128), 256>>>(bih, bhh);

    // ---- persistent recurrence (all 256 steps) ----
    recur_kernel<<<NBLK, 256, DSMEM_BYTES>>>(c0, out);

    // ---- tail (raw h_T) then softmax ----
    tail_kernel<<<(BB * HH + 255) / 256, 256>>>(out);
    softmax_kernel<<<TT * BB, 256>>>(out);
}